// round 7
// baseline (speedup 1.0000x reference)
#include <cuda_runtime.h>
#include <cuda_bf16.h>
#include <cuda_fp16.h>
#include <cstdint>

// Problem constants
#define BB   2
#define TT   2048
#define DIMC 1024
#define NH   16
#define HD   64
#define MTOT (BB * TT)          // 4096
#define N_QKV (3 * DIMC)        // 3072

// q pre-scale: 1/sqrt(64) * log2(e)
#define QSCALE 0.18033688011112042f

// -------- scratch (device globals; no allocation allowed) --------
__device__ __half g_qh[BB * NH * TT * HD], g_ql[BB * NH * TT * HD];
__device__ __half g_kh[BB * NH * TT * HD];
__device__ __half g_vh[BB * NH * TT * HD];
__device__ __nv_bfloat16 g_xh[MTOT * DIMC], g_xl[MTOT * DIMC];        // x
__device__ __nv_bfloat16 g_ah[MTOT * DIMC], g_al[MTOT * DIMC];        // attn out [B,T,C]
__device__ __nv_bfloat16 g_wqh[N_QKV * DIMC], g_wql[N_QKV * DIMC];    // W_qkv^T
__device__ __nv_bfloat16 g_woh[DIMC * DIMC], g_wol[DIMC * DIMC];      // W_out^T

// ============================================================================
// Helpers (plain-target PTX: cp.async / ldmatrix / mma.sync)
// ============================================================================
__device__ __forceinline__ uint32_t smem_u32(const void* p) {
    uint32_t a;
    asm("{ .reg .u64 t; cvta.to.shared.u64 t, %1; cvt.u32.u64 %0, t; }" : "=r"(a) : "l"(p));
    return a;
}
__device__ __forceinline__ void cp16(uint32_t dst, const void* src) {
    asm volatile("cp.async.cg.shared.global [%0], [%1], 16;" :: "r"(dst), "l"(src));
}
__device__ __forceinline__ void cp_commit() { asm volatile("cp.async.commit_group;" ::: "memory"); }
__device__ __forceinline__ void cp_wait0()  { asm volatile("cp.async.wait_group 0;" ::: "memory"); }
__device__ __forceinline__ void cp_wait1()  { asm volatile("cp.async.wait_group 1;" ::: "memory"); }

__device__ __forceinline__ void ldsm4(uint32_t& r0, uint32_t& r1, uint32_t& r2, uint32_t& r3,
                                      uint32_t addr) {
    asm volatile("ldmatrix.sync.aligned.m8n8.x4.shared.b16 {%0,%1,%2,%3}, [%4];"
                 : "=r"(r0), "=r"(r1), "=r"(r2), "=r"(r3) : "r"(addr));
}
__device__ __forceinline__ void ldsm4t(uint32_t& r0, uint32_t& r1, uint32_t& r2, uint32_t& r3,
                                       uint32_t addr) {
    asm volatile("ldmatrix.sync.aligned.m8n8.x4.trans.shared.b16 {%0,%1,%2,%3}, [%4];"
                 : "=r"(r0), "=r"(r1), "=r"(r2), "=r"(r3) : "r"(addr));
}
__device__ __forceinline__ void mma_bf(float* c, const uint32_t* a, uint32_t b0, uint32_t b1) {
    asm volatile(
        "mma.sync.aligned.m16n8k16.row.col.f32.bf16.bf16.f32 "
        "{%0,%1,%2,%3}, {%4,%5,%6,%7}, {%8,%9}, {%0,%1,%2,%3};"
        : "+f"(c[0]), "+f"(c[1]), "+f"(c[2]), "+f"(c[3])
        : "r"(a[0]), "r"(a[1]), "r"(a[2]), "r"(a[3]), "r"(b0), "r"(b1));
}
__device__ __forceinline__ void mma_fp(float* c, const uint32_t* a, uint32_t b0, uint32_t b1) {
    asm volatile(
        "mma.sync.aligned.m16n8k16.row.col.f32.f16.f16.f32 "
        "{%0,%1,%2,%3}, {%4,%5,%6,%7}, {%8,%9}, {%0,%1,%2,%3};"
        : "+f"(c[0]), "+f"(c[1]), "+f"(c[2]), "+f"(c[3])
        : "r"(a[0]), "r"(a[1]), "r"(a[2]), "r"(a[3]), "r"(b0), "r"(b1));
}

// exp2 on FFMA pipe: magic-number round + degree-5 Taylor, t <= 0
__device__ __forceinline__ float exp2p(float t) {
    t = fmaxf(t, -80.0f);
    float k = t + 12582912.0f;
    int ik = __float_as_int(k) << 23;
    float f = t - (k - 12582912.0f);
    float r = 1.3333558146e-3f;
    r = fmaf(r, f, 9.6181291076e-3f);
    r = fmaf(r, f, 5.5504108664e-2f);
    r = fmaf(r, f, 2.4022650696e-1f);
    r = fmaf(r, f, 6.9314718056e-1f);
    r = fmaf(r, f, 1.0f);
    return __int_as_float(__float_as_int(r) + ik);
}

__device__ __forceinline__ uint32_t packh2(__half a, __half b) {
    __half2 h = __halves2half2(a, b);
    return *(uint32_t*)&h;
}
__device__ __forceinline__ void split2h(float a, float b, uint32_t& hi, uint32_t& lo) {
    __half ha = __float2half_rn(a), hb = __float2half_rn(b);
    hi = packh2(ha, hb);
    lo = packh2(__float2half_rn(a - __half2float(ha)),
                __float2half_rn(b - __half2float(hb)));
}

// ============================================================================
// fp32 -> bf16 split conversion (x), vectorized float4
// ============================================================================
__global__ void split_kernel(const float* __restrict__ src) {
    int i = (blockIdx.x * blockDim.x + threadIdx.x) * 4;
    float4 v = *(const float4*)(src + i);
    __nv_bfloat16 h0 = __float2bfloat16(v.x), h1 = __float2bfloat16(v.y);
    __nv_bfloat16 h2 = __float2bfloat16(v.z), h3 = __float2bfloat16(v.w);
    __nv_bfloat162 hi0 = {h0, h1}, hi1 = {h2, h3};
    __nv_bfloat162 lo0 = {__float2bfloat16(v.x - __bfloat162float(h0)),
                          __float2bfloat16(v.y - __bfloat162float(h1))};
    __nv_bfloat162 lo1 = {__float2bfloat16(v.z - __bfloat162float(h2)),
                          __float2bfloat16(v.w - __bfloat162float(h3))};
    *(__nv_bfloat162*)(g_xh + i) = hi0;
    *(__nv_bfloat162*)(g_xh + i + 2) = hi1;
    *(__nv_bfloat162*)(g_xl + i) = lo0;
    *(__nv_bfloat162*)(g_xl + i + 2) = lo1;
}

// ============================================================================
// W[K=1024, N] -> W^T split into [N, 1024] bf16 hi/lo
// ============================================================================
template <int W>
__global__ void transpose_split(const float* __restrict__ Win) {
    const int N = (W == 0) ? N_QKV : DIMC;
    __nv_bfloat16* Th = (W == 0) ? g_wqh : g_woh;
    __nv_bfloat16* Tl = (W == 0) ? g_wql : g_wol;
    __shared__ float t[32][33];
    int tx = threadIdx.x, ty = threadIdx.y;
    int n0 = blockIdx.x * 32, k0 = blockIdx.y * 32;
#pragma unroll
    for (int j = 0; j < 32; j += 8)
        t[ty + j][tx] = Win[(size_t)(k0 + ty + j) * N + n0 + tx];
    __syncthreads();
#pragma unroll
    for (int j = 0; j < 32; j += 8) {
        float v = t[tx][ty + j];
        size_t o = (size_t)(n0 + ty + j) * DIMC + k0 + tx;
        __nv_bfloat16 h = __float2bfloat16(v);
        Th[o] = h;
        Tl[o] = __float2bfloat16(v - __bfloat162float(h));
    }
}

// ============================================================================
// HMMA split-bf16 GEMM: 128x128 CTA tile, BK=32, 2-stage cp.async.
// 4 warps (2x2), 64x64 warp tiles, B fragments via ldsm4 pairs.
// MODE 1 epilogue -> fp16 Q hi/lo (+pos,scaled), K hi, V hi.
// MODE 0 -> fp32 Cout + bias.
// ============================================================================
#define PADK   40                  // 32 + 8 bf16 padding (80B rows)
#define MAT_B  (128 * PADK * 2)    // 10240 B
#define STG_B  (4 * MAT_B)         // 40960 B
#define GEMM_SMEM (2 * STG_B)      // 81920 B

template <int MODE>
__global__ __launch_bounds__(128) void hmma_gemm(
    const float* __restrict__ bias, const float* __restrict__ pos,
    float* __restrict__ Cout)
{
    const __nv_bfloat16* Ah = (MODE == 1) ? g_xh : g_ah;
    const __nv_bfloat16* Al = (MODE == 1) ? g_xl : g_al;
    const __nv_bfloat16* Bh = (MODE == 1) ? g_wqh : g_woh;
    const __nv_bfloat16* Bl = (MODE == 1) ? g_wql : g_wol;

    extern __shared__ char smraw[];
    const uint32_t sbase = smem_u32(smraw);

    const int tid = threadIdx.x;
    const int wid = tid >> 5, lane = tid & 31;
    const int wm0 = (wid >> 1) * 64;     // 0 or 64
    const int wn0 = (wid & 1) * 64;      // 0 or 64

    const int row0 = blockIdx.y * 128;
    const int col0 = blockIdx.x * 128;

    const __nv_bfloat16* srcs[4] = {
        Ah + (size_t)row0 * DIMC, Al + (size_t)row0 * DIMC,
        Bh + (size_t)col0 * DIMC, Bl + (size_t)col0 * DIMC };

    // per chunk: 4 mats * 128 rows * 4 x 16B = 2048 cp16 / 128 thr = 16 each
    const int lr0 = tid >> 2;            // 0..31
    const int lch = tid & 3;             // 16B chunk in 64B row

    auto load_chunk = [&](int kc, int s) {
        uint32_t st = sbase + (uint32_t)s * STG_B;
#pragma unroll
        for (int mmat = 0; mmat < 4; ++mmat) {
            const __nv_bfloat16* src = srcs[mmat] + (size_t)kc * 32;
            uint32_t mb = st + (uint32_t)mmat * MAT_B;
#pragma unroll
            for (int i = 0; i < 4; ++i) {
                int r = lr0 + i * 32;
                cp16(mb + (uint32_t)(r * PADK + lch * 8) * 2,
                     src + (size_t)r * DIMC + lch * 8);
            }
        }
    };

    float acc[4][8][4];
#pragma unroll
    for (int i = 0; i < 4; ++i)
#pragma unroll
        for (int j = 0; j < 8; ++j)
#pragma unroll
            for (int k = 0; k < 4; ++k) acc[i][j][k] = 0.0f;

    const int aRow = lane & 15;               // x4 ldsm row addressing
    const int aColHalf = (lane >> 4) * 8;     // k-half

    load_chunk(0, 0);
    cp_commit();

    const int NC = DIMC / 32;   // 32
    for (int kc = 0; kc < NC; ++kc) {
        int cur = kc & 1;
        if (kc + 1 < NC) {
            load_chunk(kc + 1, cur ^ 1);
            cp_commit();
            cp_wait1();
        } else {
            cp_wait0();
        }
        __syncthreads();

        uint32_t st = sbase + (uint32_t)cur * STG_B;
        uint32_t aH = st, aL = st + MAT_B, bH = st + 2 * MAT_B, bL = st + 3 * MAT_B;

#pragma unroll
        for (int ks = 0; ks < 2; ++ks) {
            int kcol = ks * 16;
            // A fragments (hi+lo), 64 rows = 4 frags each
            uint32_t ah[4][4], al[4][4];
#pragma unroll
            for (int mf = 0; mf < 4; ++mf) {
                uint32_t off = (uint32_t)((wm0 + mf * 16 + aRow) * PADK + kcol + aColHalf) * 2;
                ldsm4(ah[mf][0], ah[mf][1], ah[mf][2], ah[mf][3], aH + off);
                ldsm4(al[mf][0], al[mf][1], al[mf][2], al[mf][3], aL + off);
            }
            // B pairs: ldsm4 covers 16 n-rows x 16 k -> frags (2np, 2np+1)
#pragma unroll
            for (int np = 0; np < 4; ++np) {
                uint32_t off = (uint32_t)((wn0 + np * 16 + aRow) * PADK + kcol + aColHalf) * 2;
                uint32_t h0, h1, h2, h3, l0, l1, l2, l3;
                ldsm4(h0, h1, h2, h3, bH + off);
                ldsm4(l0, l1, l2, l3, bL + off);
                // frag f0 = (h0, h2) [n np*16+0..7], f1 = (h1, h3) [n +8..15]
#pragma unroll
                for (int mf = 0; mf < 4; ++mf) {
                    float* a0 = acc[mf][2 * np];
                    float* a1 = acc[mf][2 * np + 1];
                    mma_bf(a0, ah[mf], h0, h2);
                    mma_bf(a0, ah[mf], l0, l2);
                    mma_bf(a0, al[mf], h0, h2);
                    mma_bf(a1, ah[mf], h1, h3);
                    mma_bf(a1, ah[mf], l1, l3);
                    mma_bf(a1, al[mf], h1, h3);
                }
            }
        }
        __syncthreads();
    }

    const int erow = lane >> 2;
    const int ecol = (lane & 3) * 2;
#pragma unroll
    for (int mf = 0; mf < 4; ++mf) {
#pragma unroll
        for (int half = 0; half < 2; ++half) {
            int m = row0 + wm0 + mf * 16 + erow + half * 8;
            int b_ = m >> 11, t = m & (TT - 1);
#pragma unroll
            for (int nf = 0; nf < 8; ++nf) {
                int n = col0 + wn0 + nf * 8 + ecol;
                float vx = acc[mf][nf][half * 2 + 0] + bias[n + 0];
                float vy = acc[mf][nf][half * 2 + 1] + bias[n + 1];
                if (MODE == 0) {
                    float2 v = {vx, vy};
                    *(float2*)(Cout + (size_t)m * DIMC + n) = v;
                } else {
                    int sec = n >> 10;
                    int cc = n & (DIMC - 1);
                    int h = cc >> 6, d = cc & 63;
                    size_t idx = (((size_t)(b_ * NH + h)) * TT + t) * HD + d;
                    if (sec == 0) {
                        float qx = (vx + pos[cc + 0]) * QSCALE;
                        float qy = (vy + pos[cc + 1]) * QSCALE;
                        uint32_t hi, lo;
                        split2h(qx, qy, hi, lo);
                        *(uint32_t*)(g_qh + idx) = hi;
                        *(uint32_t*)(g_ql + idx) = lo;
                    } else if (sec == 1) {
                        *(uint32_t*)(g_kh + idx) =
                            packh2(__float2half_rn(vx), __float2half_rn(vy));
                    } else {
                        *(uint32_t*)(g_vh + idx) =
                            packh2(__float2half_rn(vx), __float2half_rn(vy));
                    }
                }
            }
        }
    }
}

// ============================================================================
// HMMA flash attention (round-6, unchanged): 128 q-rows/CTA, Bc=64.
// Q,P exact fp16 hi+lo (2 products); K,V single fp16.
// ============================================================================
#define AT_PADH 72                      // fp16 elems per smem row (144 B)
#define Q_BYTES (128 * AT_PADH * 2)     // 18432
#define KV_MAT  (64 * AT_PADH * 2)      // 9216
#define KV_STAGE (2 * KV_MAT)           // 18432 (Kh, Vh)
#define ATT_SMEM (2 * Q_BYTES + 2 * KV_STAGE)   // 73728

__global__ __launch_bounds__(256) void attn2()
{
    extern __shared__ char smraw[];
    const uint32_t sb = smem_u32(smraw);
    const uint32_t sQh = sb, sQl = sb + Q_BYTES;
    const uint32_t sKV = sb + 2 * Q_BYTES;

    const int tid = threadIdx.x;
    const int lane = tid & 31;
    const int qi = gridDim.x - 1 - blockIdx.x;
    const int bh = blockIdx.y;
    const int q0 = qi * 128;
    const int qr0 = (tid >> 5) * 16;

    const __half* qhp = g_qh + (size_t)bh * TT * HD;
    const __half* qlp = g_ql + (size_t)bh * TT * HD;
    const __half* kvsrc[2] = {
        g_kh + (size_t)bh * TT * HD, g_vh + (size_t)bh * TT * HD };

    auto prefetchKV = [&](int j, uint32_t dst) {
        int kb = j * 64;
#pragma unroll
        for (int i = 0; i < 4; ++i) {
            int c = tid + i * 256;
            int mat = c >> 9, rem = c & 511;
            int r = rem >> 3, ch = rem & 7;
            cp16(dst + (uint32_t)mat * KV_MAT + (uint32_t)(r * 144 + ch * 16),
                 kvsrc[mat] + (size_t)(kb + r) * HD + ch * 8);
        }
    };

#pragma unroll
    for (int i = 0; i < 4; ++i) {
        int c = tid + i * 256;
        int r = c >> 3, ch = c & 7;
        cp16(sQh + (uint32_t)(r * 144 + ch * 16), qhp + (size_t)(q0 + r) * HD + ch * 8);
        cp16(sQl + (uint32_t)(r * 144 + ch * 16), qlp + (size_t)(q0 + r) * HD + ch * 8);
    }
    prefetchKV(0, sKV);
    cp_commit();
    cp_wait0();
    __syncthreads();

    uint32_t fqh[4][4], fql[4][4];
    {
        int rr = qr0 + (lane & 15);
#pragma unroll
        for (int kf = 0; kf < 4; ++kf) {
            int cc = kf * 16 + ((lane & 16) ? 8 : 0);
            uint32_t off = (uint32_t)(rr * 144 + cc * 2);
            ldsm4(fqh[kf][0], fqh[kf][1], fqh[kf][2], fqh[kf][3], sQh + off);
            ldsm4(fql[kf][0], fql[kf][1], fql[kf][2], fql[kf][3], sQl + off);
        }
    }

    float o[8][4];
#pragma unroll
    for (int i = 0; i < 8; ++i)
#pragma unroll
        for (int k = 0; k < 4; ++k) o[i][k] = 0.0f;
    float m0 = -1e30f, m1 = -1e30f, l0 = 0.0f, l1 = 0.0f;

    const int ntiles = 2 * qi + 2;
    for (int j = 0; j < ntiles; ++j) {
        uint32_t stage = sKV + (uint32_t)(j & 1) * KV_STAGE;
        if (j + 1 < ntiles) {
            prefetchKV(j + 1, sKV + (uint32_t)((j + 1) & 1) * KV_STAGE);
            cp_commit();
        }

        float c[8][4];
#pragma unroll
        for (int i = 0; i < 8; ++i)
#pragma unroll
            for (int k = 0; k < 4; ++k) c[i][k] = 0.0f;

        uint32_t Kh = stage;
        {
            int rb = ((lane & 16) ? 8 : 0) + (lane & 7);
            int cb = ((lane & 8) ? 8 : 0);
#pragma unroll
            for (int kf = 0; kf < 4; ++kf) {
#pragma unroll
                for (int jp = 0; jp < 4; ++jp) {
                    uint32_t off = (uint32_t)((jp * 16 + rb) * 144 + (kf * 16 + cb) * 2);
                    uint32_t h0, h1, h2, h3;
                    ldsm4(h0, h1, h2, h3, Kh + off);
                    mma_fp(c[2 * jp],     fqh[kf], h0, h1);
                    mma_fp(c[2 * jp],     fql[kf], h0, h1);
                    mma_fp(c[2 * jp + 1], fqh[kf], h2, h3);
                    mma_fp(c[2 * jp + 1], fql[kf], h2, h3);
                }
            }
        }

        if (j >= 2 * qi) {
            int row0 = q0 + qr0 + (lane >> 2);
            int kb = j * 64 + (lane & 3) * 2;
#pragma unroll
            for (int nf = 0; nf < 8; ++nf) {
                int key = kb + nf * 8;
                if (key     > row0)     c[nf][0] = -1e30f;
                if (key + 1 > row0)     c[nf][1] = -1e30f;
                if (key     > row0 + 8) c[nf][2] = -1e30f;
                if (key + 1 > row0 + 8) c[nf][3] = -1e30f;
            }
        }

        float v0 = -1e30f, v1 = -1e30f;
#pragma unroll
        for (int nf = 0; nf < 8; ++nf) {
            v0 = fmaxf(v0, fmaxf(c[nf][0], c[nf][1]));
            v1 = fmaxf(v1, fmaxf(c[nf][2], c[nf][3]));
        }
        v0 = fmaxf(v0, __shfl_xor_sync(0xFFFFFFFFu, v0, 1));
        v0 = fmaxf(v0, __shfl_xor_sync(0xFFFFFFFFu, v0, 2));
        v1 = fmaxf(v1, __shfl_xor_sync(0xFFFFFFFFu, v1, 1));
        v1 = fmaxf(v1, __shfl_xor_sync(0xFFFFFFFFu, v1, 2));
        float mn0 = fmaxf(m0, v0), mn1 = fmaxf(m1, v1);
        float a0 = exp2p(m0 - mn0), a1 = exp2p(m1 - mn1);
        m0 = mn0; m1 = mn1;
        l0 *= a0; l1 *= a1;
#pragma unroll
        for (int nf = 0; nf < 8; ++nf) {
            o[nf][0] *= a0; o[nf][1] *= a0;
            o[nf][2] *= a1; o[nf][3] *= a1;
        }

        uint32_t Vh = stage + KV_MAT;
        int vrb = ((lane & 8) ? 8 : 0) + (lane & 7);
        int vcb = ((lane & 16) ? 8 : 0);
#pragma unroll
        for (int t = 0; t < 4; ++t) {
            float p00 = exp2p(c[2 * t][0] - m0), p01 = exp2p(c[2 * t][1] - m0);
            float p02 = exp2p(c[2 * t][2] - m1), p03 = exp2p(c[2 * t][3] - m1);
            float p10 = exp2p(c[2 * t + 1][0] - m0), p11 = exp2p(c[2 * t + 1][1] - m0);
            float p12 = exp2p(c[2 * t + 1][2] - m1), p13 = exp2p(c[2 * t + 1][3] - m1);
            l0 += p00 + p01 + p10 + p11;
            l1 += p02 + p03 + p12 + p13;

            uint32_t ph[4], pl[4];
            split2h(p00, p01, ph[0], pl[0]);
            split2h(p02, p03, ph[1], pl[1]);
            split2h(p10, p11, ph[2], pl[2]);
            split2h(p12, p13, ph[3], pl[3]);

#pragma unroll
            for (int dp = 0; dp < 4; ++dp) {
                uint32_t off = (uint32_t)((t * 16 + vrb) * 144 + (dp * 16 + vcb) * 2);
                uint32_t h0, h1, h2, h3;
                ldsm4t(h0, h1, h2, h3, Vh + off);
                mma_fp(o[2 * dp],     ph, h0, h1);
                mma_fp(o[2 * dp],     pl, h0, h1);
                mma_fp(o[2 * dp + 1], ph, h2, h3);
                mma_fp(o[2 * dp + 1], pl, h2, h3);
            }
        }

        if (j + 1 < ntiles) cp_wait0();
        __syncthreads();
    }

    l0 += __shfl_xor_sync(0xFFFFFFFFu, l0, 1);
    l0 += __shfl_xor_sync(0xFFFFFFFFu, l0, 2);
    l1 += __shfl_xor_sync(0xFFFFFFFFu, l1, 1);
    l1 += __shfl_xor_sync(0xFFFFFFFFu, l1, 2);
    float inv0 = 1.0f / l0, inv1 = 1.0f / l1;

    int b_ = bh >> 4, h = bh & 15;
    int t0 = q0 + qr0 + (lane >> 2);
    size_t r0 = ((size_t)b_ * TT + t0) * DIMC;
    size_t r1 = r0 + (size_t)8 * DIMC;
    int coff = h * 64 + (lane & 3) * 2;
#pragma unroll
    for (int nf = 0; nf < 8; ++nf) {
        int col = coff + nf * 8;
        float x0 = o[nf][0] * inv0, y0 = o[nf][1] * inv0;
        float x1 = o[nf][2] * inv1, y1 = o[nf][3] * inv1;
        __nv_bfloat16 hx0 = __float2bfloat16(x0), hy0 = __float2bfloat16(y0);
        __nv_bfloat16 hx1 = __float2bfloat16(x1), hy1 = __float2bfloat16(y1);
        __nv_bfloat162 hi0 = {hx0, hy0}, hi1 = {hx1, hy1};
        __nv_bfloat162 lo0 = {__float2bfloat16(x0 - __bfloat162float(hx0)),
                              __float2bfloat16(y0 - __bfloat162float(hy0))};
        __nv_bfloat162 lo1 = {__float2bfloat16(x1 - __bfloat162float(hx1)),
                              __float2bfloat16(y1 - __bfloat162float(hy1))};
        *(__nv_bfloat162*)(g_ah + r0 + col) = hi0;
        *(__nv_bfloat162*)(g_al + r0 + col) = lo0;
        *(__nv_bfloat162*)(g_ah + r1 + col) = hi1;
        *(__nv_bfloat162*)(g_al + r1 + col) = lo1;
    }
}

// ============================================================================
// Launch
// ============================================================================
extern "C" void kernel_launch(void* const* d_in, const int* in_sizes, int n_in,
                              void* d_out, int out_size)
{
    (void)in_sizes; (void)n_in; (void)out_size;
    const float* x     = (const float*)d_in[0];
    const float* w_qkv = (const float*)d_in[1];
    const float* b_qkv = (const float*)d_in[2];
    const float* w_out = (const float*)d_in[3];
    const float* b_out = (const float*)d_in[4];
    const float* pos   = (const float*)d_in[5];
    float* out = (float*)d_out;

    cudaFuncSetAttribute(hmma_gemm<1>, cudaFuncAttributeMaxDynamicSharedMemorySize, GEMM_SMEM);
    cudaFuncSetAttribute(hmma_gemm<0>, cudaFuncAttributeMaxDynamicSharedMemorySize, GEMM_SMEM);
    cudaFuncSetAttribute(attn2, cudaFuncAttributeMaxDynamicSharedMemorySize, ATT_SMEM);

    // 0) split input + transpose/split weights
    split_kernel<<<MTOT * DIMC / 1024, 256>>>(x);
    transpose_split<0><<<dim3(N_QKV / 32, DIMC / 32), dim3(32, 8)>>>(w_qkv);
    transpose_split<1><<<dim3(DIMC / 32, DIMC / 32), dim3(32, 8)>>>(w_out);

    // 1) QKV projection + bias (+pos, q-scale) -> fp16 Q hi/lo, K, V
    hmma_gemm<1><<<dim3(N_QKV / 128, MTOT / 128), 128, GEMM_SMEM>>>(b_qkv, pos, nullptr);

    // 2) HMMA flash attention -> bf16 split attn out
    attn2<<<dim3(TT / 128, BB * NH), 256, ATT_SMEM>>>();

    // 3) output projection + bias
    hmma_gemm<0><<<dim3(DIMC / 128, MTOT / 128), 128, GEMM_SMEM>>>(b_out, nullptr, out);
}

// round 8
// speedup vs baseline: 1.3160x; 1.3160x over previous
#include <cuda_runtime.h>
#include <cuda_bf16.h>
#include <cuda_fp16.h>
#include <cstdint>

// Problem constants
#define BB   2
#define TT   2048
#define DIMC 1024
#define NH   16
#define HD   64
#define MTOT (BB * TT)          // 4096
#define N_QKV (3 * DIMC)        // 3072

// q pre-scale: 1/sqrt(64) * log2(e)
#define QSCALE 0.18033688011112042f

// -------- scratch (device globals; no allocation allowed) --------
__device__ __half g_qh[BB * NH * TT * HD], g_ql[BB * NH * TT * HD];
__device__ __half g_kh[BB * NH * TT * HD];
__device__ __half g_vh[BB * NH * TT * HD];
__device__ __half g_xh[MTOT * DIMC];          // x (fp16)
__device__ __half g_ah[MTOT * DIMC];          // attn out [B,T,C] (fp16)
__device__ __half g_wqh[N_QKV * DIMC], g_wql[N_QKV * DIMC];    // W_qkv^T hi/lo
__device__ __half g_woh[DIMC * DIMC], g_wol[DIMC * DIMC];      // W_out^T hi/lo

// ============================================================================
// Helpers (plain-target PTX: cp.async / ldmatrix / mma.sync)
// ============================================================================
__device__ __forceinline__ uint32_t smem_u32(const void* p) {
    uint32_t a;
    asm("{ .reg .u64 t; cvta.to.shared.u64 t, %1; cvt.u32.u64 %0, t; }" : "=r"(a) : "l"(p));
    return a;
}
__device__ __forceinline__ void cp16(uint32_t dst, const void* src) {
    asm volatile("cp.async.cg.shared.global [%0], [%1], 16;" :: "r"(dst), "l"(src));
}
__device__ __forceinline__ void cp_commit() { asm volatile("cp.async.commit_group;" ::: "memory"); }
__device__ __forceinline__ void cp_wait0()  { asm volatile("cp.async.wait_group 0;" ::: "memory"); }
__device__ __forceinline__ void cp_wait1()  { asm volatile("cp.async.wait_group 1;" ::: "memory"); }

__device__ __forceinline__ void ldsm4(uint32_t& r0, uint32_t& r1, uint32_t& r2, uint32_t& r3,
                                      uint32_t addr) {
    asm volatile("ldmatrix.sync.aligned.m8n8.x4.shared.b16 {%0,%1,%2,%3}, [%4];"
                 : "=r"(r0), "=r"(r1), "=r"(r2), "=r"(r3) : "r"(addr));
}
__device__ __forceinline__ void ldsm4t(uint32_t& r0, uint32_t& r1, uint32_t& r2, uint32_t& r3,
                                       uint32_t addr) {
    asm volatile("ldmatrix.sync.aligned.m8n8.x4.trans.shared.b16 {%0,%1,%2,%3}, [%4];"
                 : "=r"(r0), "=r"(r1), "=r"(r2), "=r"(r3) : "r"(addr));
}
__device__ __forceinline__ void ldsm2(uint32_t& r0, uint32_t& r1, uint32_t addr) {
    asm volatile("ldmatrix.sync.aligned.m8n8.x2.shared.b16 {%0,%1}, [%2];"
                 : "=r"(r0), "=r"(r1) : "r"(addr));
}
__device__ __forceinline__ void mma_fp(float* c, const uint32_t* a, uint32_t b0, uint32_t b1) {
    asm volatile(
        "mma.sync.aligned.m16n8k16.row.col.f32.f16.f16.f32 "
        "{%0,%1,%2,%3}, {%4,%5,%6,%7}, {%8,%9}, {%0,%1,%2,%3};"
        : "+f"(c[0]), "+f"(c[1]), "+f"(c[2]), "+f"(c[3])
        : "r"(a[0]), "r"(a[1]), "r"(a[2]), "r"(a[3]), "r"(b0), "r"(b1));
}

// exp2 on FFMA pipe: magic-number round + degree-5 Taylor, t <= 0
__device__ __forceinline__ float exp2p(float t) {
    t = fmaxf(t, -80.0f);
    float k = t + 12582912.0f;
    int ik = __float_as_int(k) << 23;
    float f = t - (k - 12582912.0f);
    float r = 1.3333558146e-3f;
    r = fmaf(r, f, 9.6181291076e-3f);
    r = fmaf(r, f, 5.5504108664e-2f);
    r = fmaf(r, f, 2.4022650696e-1f);
    r = fmaf(r, f, 6.9314718056e-1f);
    r = fmaf(r, f, 1.0f);
    return __int_as_float(__float_as_int(r) + ik);
}

__device__ __forceinline__ uint32_t packh2(__half a, __half b) {
    __half2 h = __halves2half2(a, b);
    return *(uint32_t*)&h;
}
__device__ __forceinline__ void split2h(float a, float b, uint32_t& hi, uint32_t& lo) {
    __half ha = __float2half_rn(a), hb = __float2half_rn(b);
    hi = packh2(ha, hb);
    lo = packh2(__float2half_rn(a - __half2float(ha)),
                __float2half_rn(b - __half2float(hb)));
}

// ============================================================================
// fp32 -> fp16 conversion (x), vectorized float4
// ============================================================================
__global__ void conv_kernel(const float* __restrict__ src) {
    int i = (blockIdx.x * blockDim.x + threadIdx.x) * 4;
    float4 v = *(const float4*)(src + i);
    *(uint32_t*)(g_xh + i)     = packh2(__float2half_rn(v.x), __float2half_rn(v.y));
    *(uint32_t*)(g_xh + i + 2) = packh2(__float2half_rn(v.z), __float2half_rn(v.w));
}

// ============================================================================
// W[K=1024, N] -> W^T split into [N, 1024] fp16 hi/lo
// ============================================================================
template <int W>
__global__ void transpose_split(const float* __restrict__ Win) {
    const int N = (W == 0) ? N_QKV : DIMC;
    __half* Th = (W == 0) ? g_wqh : g_woh;
    __half* Tl = (W == 0) ? g_wql : g_wol;
    __shared__ float t[32][33];
    int tx = threadIdx.x, ty = threadIdx.y;
    int n0 = blockIdx.x * 32, k0 = blockIdx.y * 32;
#pragma unroll
    for (int j = 0; j < 32; j += 8)
        t[ty + j][tx] = Win[(size_t)(k0 + ty + j) * N + n0 + tx];
    __syncthreads();
#pragma unroll
    for (int j = 0; j < 32; j += 8) {
        float v = t[tx][ty + j];
        size_t o = (size_t)(n0 + ty + j) * DIMC + k0 + tx;
        __half h = __float2half_rn(v);
        Th[o] = h;
        Tl[o] = __float2half_rn(v - __half2float(h));
    }
}

// ============================================================================
// HMMA fp16 GEMM: C = Ah·(Bh+Bl), A fp16 plain, B fp16 hi/lo (weights exact).
// Round-4/6 proven skeleton: 128x128 CTA, BK=32, 2-stage cp.async,
// 8 warps (2x4), 64x32 warp tiles. 2 products per fragment.
// MODE 1 -> fp16 Q hi/lo (+pos,scaled), K, V. MODE 0 -> fp32 Cout + bias.
// ============================================================================
#define PADK   40                  // 32 + 8 fp16 padding (80B rows)
#define MAT_B  (128 * PADK * 2)    // 10240 B
#define STG_B  (3 * MAT_B)         // 30720 B (A, Bh, Bl)
#define GEMM_SMEM (2 * STG_B)      // 61440 B

template <int MODE>
__global__ __launch_bounds__(256) void hmma_gemm(
    const float* __restrict__ bias, const float* __restrict__ pos,
    float* __restrict__ Cout)
{
    const __half* Aa = (MODE == 1) ? g_xh : g_ah;
    const __half* Bh = (MODE == 1) ? g_wqh : g_woh;
    const __half* Bl = (MODE == 1) ? g_wql : g_wol;

    extern __shared__ char smraw[];
    const uint32_t sbase = smem_u32(smraw);

    const int tid = threadIdx.x;
    const int wid = tid >> 5, lane = tid & 31;
    const int wm0 = (wid >> 2) * 64;
    const int wn0 = (wid & 3) * 32;

    const int row0 = blockIdx.y * 128;
    const int col0 = blockIdx.x * 128;

    const __half* srcs[3] = {
        Aa + (size_t)row0 * DIMC,
        Bh + (size_t)col0 * DIMC,
        Bl + (size_t)col0 * DIMC };

    const int lr0 = tid >> 2;           // 0..63, 2 passes -> 128 rows
    const int lch = tid & 3;            // 16B chunk in 64B row

    auto load_chunk = [&](int kc, int s) {
        uint32_t st = sbase + (uint32_t)s * STG_B;
#pragma unroll
        for (int mmat = 0; mmat < 3; ++mmat) {
            const __half* src = srcs[mmat] + (size_t)kc * 32;
            uint32_t mb = st + (uint32_t)mmat * MAT_B;
#pragma unroll
            for (int i = 0; i < 2; ++i) {
                int r = lr0 + i * 64;
                cp16(mb + (uint32_t)(r * PADK + lch * 8) * 2,
                     src + (size_t)r * DIMC + lch * 8);
            }
        }
    };

    float acc[4][4][4];
#pragma unroll
    for (int i = 0; i < 4; ++i)
#pragma unroll
        for (int j = 0; j < 4; ++j)
#pragma unroll
            for (int k = 0; k < 4; ++k) acc[i][j][k] = 0.0f;

    const int aRow = lane & 15;
    const int aColHalf = (lane >> 4) * 8;
    const int bRow = lane & 7;
    const int bColHalf = ((lane >> 3) & 1) * 8;

    load_chunk(0, 0);
    cp_commit();

    const int NC = DIMC / 32;
    for (int kc = 0; kc < NC; ++kc) {
        int cur = kc & 1;
        if (kc + 1 < NC) {
            load_chunk(kc + 1, cur ^ 1);
            cp_commit();
            cp_wait1();
        } else {
            cp_wait0();
        }
        __syncthreads();

        uint32_t st = sbase + (uint32_t)cur * STG_B;
        uint32_t aA = st, bH = st + MAT_B, bL = st + 2 * MAT_B;

#pragma unroll
        for (int ks = 0; ks < 2; ++ks) {
            uint32_t ah[4][4], bh[4][2], bl[4][2];
            int kcol = ks * 16;
#pragma unroll
            for (int mf = 0; mf < 4; ++mf) {
                uint32_t off = (uint32_t)((wm0 + mf * 16 + aRow) * PADK + kcol + aColHalf) * 2;
                ldsm4(ah[mf][0], ah[mf][1], ah[mf][2], ah[mf][3], aA + off);
            }
#pragma unroll
            for (int nf = 0; nf < 4; ++nf) {
                uint32_t off = (uint32_t)((wn0 + nf * 8 + bRow) * PADK + kcol + bColHalf) * 2;
                ldsm2(bh[nf][0], bh[nf][1], bH + off);
                ldsm2(bl[nf][0], bl[nf][1], bL + off);
            }
#pragma unroll
            for (int mf = 0; mf < 4; ++mf)
#pragma unroll
                for (int nf = 0; nf < 4; ++nf) {
                    mma_fp(acc[mf][nf], ah[mf], bh[nf][0], bh[nf][1]);
                    mma_fp(acc[mf][nf], ah[mf], bl[nf][0], bl[nf][1]);
                }
        }
        __syncthreads();
    }

    const int erow = lane >> 2;
    const int ecol = (lane & 3) * 2;
#pragma unroll
    for (int mf = 0; mf < 4; ++mf) {
#pragma unroll
        for (int half = 0; half < 2; ++half) {
            int m = row0 + wm0 + mf * 16 + erow + half * 8;
            int b_ = m >> 11, t = m & (TT - 1);
#pragma unroll
            for (int nf = 0; nf < 4; ++nf) {
                int n = col0 + wn0 + nf * 8 + ecol;
                float vx = acc[mf][nf][half * 2 + 0] + bias[n + 0];
                float vy = acc[mf][nf][half * 2 + 1] + bias[n + 1];
                if (MODE == 0) {
                    float2 v = {vx, vy};
                    *(float2*)(Cout + (size_t)m * DIMC + n) = v;
                } else {
                    int sec = n >> 10;
                    int cc = n & (DIMC - 1);
                    int h = cc >> 6, d = cc & 63;
                    size_t idx = (((size_t)(b_ * NH + h)) * TT + t) * HD + d;
                    if (sec == 0) {
                        float qx = (vx + pos[cc + 0]) * QSCALE;
                        float qy = (vy + pos[cc + 1]) * QSCALE;
                        uint32_t hi, lo;
                        split2h(qx, qy, hi, lo);
                        *(uint32_t*)(g_qh + idx) = hi;
                        *(uint32_t*)(g_ql + idx) = lo;
                    } else if (sec == 1) {
                        *(uint32_t*)(g_kh + idx) =
                            packh2(__float2half_rn(vx), __float2half_rn(vy));
                    } else {
                        *(uint32_t*)(g_vh + idx) =
                            packh2(__float2half_rn(vx), __float2half_rn(vy));
                    }
                }
            }
        }
    }
}

// ============================================================================
// HMMA flash attention (round-6 skeleton): 128 q-rows/CTA, Bc=64.
// Q,P exact fp16 hi+lo (2 products); K,V single fp16.
// Output: single fp16 g_ah.
// ============================================================================
#define AT_PADH 72                      // fp16 elems per smem row (144 B)
#define Q_BYTES (128 * AT_PADH * 2)     // 18432
#define KV_MAT  (64 * AT_PADH * 2)      // 9216
#define KV_STAGE (2 * KV_MAT)           // 18432 (Kh, Vh)
#define ATT_SMEM (2 * Q_BYTES + 2 * KV_STAGE)   // 73728

__global__ __launch_bounds__(256) void attn2()
{
    extern __shared__ char smraw[];
    const uint32_t sb = smem_u32(smraw);
    const uint32_t sQh = sb, sQl = sb + Q_BYTES;
    const uint32_t sKV = sb + 2 * Q_BYTES;

    const int tid = threadIdx.x;
    const int lane = tid & 31;
    const int qi = gridDim.x - 1 - blockIdx.x;
    const int bh = blockIdx.y;
    const int q0 = qi * 128;
    const int qr0 = (tid >> 5) * 16;

    const __half* qhp = g_qh + (size_t)bh * TT * HD;
    const __half* qlp = g_ql + (size_t)bh * TT * HD;
    const __half* kvsrc[2] = {
        g_kh + (size_t)bh * TT * HD, g_vh + (size_t)bh * TT * HD };

    auto prefetchKV = [&](int j, uint32_t dst) {
        int kb = j * 64;
#pragma unroll
        for (int i = 0; i < 4; ++i) {
            int c = tid + i * 256;
            int mat = c >> 9, rem = c & 511;
            int r = rem >> 3, ch = rem & 7;
            cp16(dst + (uint32_t)mat * KV_MAT + (uint32_t)(r * 144 + ch * 16),
                 kvsrc[mat] + (size_t)(kb + r) * HD + ch * 8);
        }
    };

#pragma unroll
    for (int i = 0; i < 4; ++i) {
        int c = tid + i * 256;
        int r = c >> 3, ch = c & 7;
        cp16(sQh + (uint32_t)(r * 144 + ch * 16), qhp + (size_t)(q0 + r) * HD + ch * 8);
        cp16(sQl + (uint32_t)(r * 144 + ch * 16), qlp + (size_t)(q0 + r) * HD + ch * 8);
    }
    prefetchKV(0, sKV);
    cp_commit();
    cp_wait0();
    __syncthreads();

    uint32_t fqh[4][4], fql[4][4];
    {
        int rr = qr0 + (lane & 15);
#pragma unroll
        for (int kf = 0; kf < 4; ++kf) {
            int cc = kf * 16 + ((lane & 16) ? 8 : 0);
            uint32_t off = (uint32_t)(rr * 144 + cc * 2);
            ldsm4(fqh[kf][0], fqh[kf][1], fqh[kf][2], fqh[kf][3], sQh + off);
            ldsm4(fql[kf][0], fql[kf][1], fql[kf][2], fql[kf][3], sQl + off);
        }
    }

    float o[8][4];
#pragma unroll
    for (int i = 0; i < 8; ++i)
#pragma unroll
        for (int k = 0; k < 4; ++k) o[i][k] = 0.0f;
    float m0 = -1e30f, m1 = -1e30f, l0 = 0.0f, l1 = 0.0f;

    const int ntiles = 2 * qi + 2;
    for (int j = 0; j < ntiles; ++j) {
        uint32_t stage = sKV + (uint32_t)(j & 1) * KV_STAGE;
        if (j + 1 < ntiles) {
            prefetchKV(j + 1, sKV + (uint32_t)((j + 1) & 1) * KV_STAGE);
            cp_commit();
        }

        float c[8][4];
#pragma unroll
        for (int i = 0; i < 8; ++i)
#pragma unroll
            for (int k = 0; k < 4; ++k) c[i][k] = 0.0f;

        uint32_t Kh = stage;
        {
            int rb = ((lane & 16) ? 8 : 0) + (lane & 7);
            int cb = ((lane & 8) ? 8 : 0);
#pragma unroll
            for (int kf = 0; kf < 4; ++kf) {
#pragma unroll
                for (int jp = 0; jp < 4; ++jp) {
                    uint32_t off = (uint32_t)((jp * 16 + rb) * 144 + (kf * 16 + cb) * 2);
                    uint32_t h0, h1, h2, h3;
                    ldsm4(h0, h1, h2, h3, Kh + off);
                    mma_fp(c[2 * jp],     fqh[kf], h0, h1);
                    mma_fp(c[2 * jp],     fql[kf], h0, h1);
                    mma_fp(c[2 * jp + 1], fqh[kf], h2, h3);
                    mma_fp(c[2 * jp + 1], fql[kf], h2, h3);
                }
            }
        }

        if (j >= 2 * qi) {
            int row0 = q0 + qr0 + (lane >> 2);
            int kb = j * 64 + (lane & 3) * 2;
#pragma unroll
            for (int nf = 0; nf < 8; ++nf) {
                int key = kb + nf * 8;
                if (key     > row0)     c[nf][0] = -1e30f;
                if (key + 1 > row0)     c[nf][1] = -1e30f;
                if (key     > row0 + 8) c[nf][2] = -1e30f;
                if (key + 1 > row0 + 8) c[nf][3] = -1e30f;
            }
        }

        float v0 = -1e30f, v1 = -1e30f;
#pragma unroll
        for (int nf = 0; nf < 8; ++nf) {
            v0 = fmaxf(v0, fmaxf(c[nf][0], c[nf][1]));
            v1 = fmaxf(v1, fmaxf(c[nf][2], c[nf][3]));
        }
        v0 = fmaxf(v0, __shfl_xor_sync(0xFFFFFFFFu, v0, 1));
        v0 = fmaxf(v0, __shfl_xor_sync(0xFFFFFFFFu, v0, 2));
        v1 = fmaxf(v1, __shfl_xor_sync(0xFFFFFFFFu, v1, 1));
        v1 = fmaxf(v1, __shfl_xor_sync(0xFFFFFFFFu, v1, 2));
        float mn0 = fmaxf(m0, v0), mn1 = fmaxf(m1, v1);
        float a0 = exp2p(m0 - mn0), a1 = exp2p(m1 - mn1);
        m0 = mn0; m1 = mn1;
        l0 *= a0; l1 *= a1;
#pragma unroll
        for (int nf = 0; nf < 8; ++nf) {
            o[nf][0] *= a0; o[nf][1] *= a0;
            o[nf][2] *= a1; o[nf][3] *= a1;
        }

        uint32_t Vh = stage + KV_MAT;
        int vrb = ((lane & 8) ? 8 : 0) + (lane & 7);
        int vcb = ((lane & 16) ? 8 : 0);
#pragma unroll
        for (int t = 0; t < 4; ++t) {
            float p00 = exp2p(c[2 * t][0] - m0), p01 = exp2p(c[2 * t][1] - m0);
            float p02 = exp2p(c[2 * t][2] - m1), p03 = exp2p(c[2 * t][3] - m1);
            float p10 = exp2p(c[2 * t + 1][0] - m0), p11 = exp2p(c[2 * t + 1][1] - m0);
            float p12 = exp2p(c[2 * t + 1][2] - m1), p13 = exp2p(c[2 * t + 1][3] - m1);
            l0 += p00 + p01 + p10 + p11;
            l1 += p02 + p03 + p12 + p13;

            uint32_t ph[4], pl[4];
            split2h(p00, p01, ph[0], pl[0]);
            split2h(p02, p03, ph[1], pl[1]);
            split2h(p10, p11, ph[2], pl[2]);
            split2h(p12, p13, ph[3], pl[3]);

#pragma unroll
            for (int dp = 0; dp < 4; ++dp) {
                uint32_t off = (uint32_t)((t * 16 + vrb) * 144 + (dp * 16 + vcb) * 2);
                uint32_t h0, h1, h2, h3;
                ldsm4t(h0, h1, h2, h3, Vh + off);
                mma_fp(o[2 * dp],     ph, h0, h1);
                mma_fp(o[2 * dp],     pl, h0, h1);
                mma_fp(o[2 * dp + 1], ph, h2, h3);
                mma_fp(o[2 * dp + 1], pl, h2, h3);
            }
        }

        if (j + 1 < ntiles) cp_wait0();
        __syncthreads();
    }

    l0 += __shfl_xor_sync(0xFFFFFFFFu, l0, 1);
    l0 += __shfl_xor_sync(0xFFFFFFFFu, l0, 2);
    l1 += __shfl_xor_sync(0xFFFFFFFFu, l1, 1);
    l1 += __shfl_xor_sync(0xFFFFFFFFu, l1, 2);
    float inv0 = 1.0f / l0, inv1 = 1.0f / l1;

    int b_ = bh >> 4, h = bh & 15;
    int t0 = q0 + qr0 + (lane >> 2);
    size_t r0 = ((size_t)b_ * TT + t0) * DIMC;
    size_t r1 = r0 + (size_t)8 * DIMC;
    int coff = h * 64 + (lane & 3) * 2;
#pragma unroll
    for (int nf = 0; nf < 8; ++nf) {
        int col = coff + nf * 8;
        *(uint32_t*)(g_ah + r0 + col) =
            packh2(__float2half_rn(o[nf][0] * inv0), __float2half_rn(o[nf][1] * inv0));
        *(uint32_t*)(g_ah + r1 + col) =
            packh2(__float2half_rn(o[nf][2] * inv1), __float2half_rn(o[nf][3] * inv1));
    }
}

// ============================================================================
// Launch
// ============================================================================
extern "C" void kernel_launch(void* const* d_in, const int* in_sizes, int n_in,
                              void* d_out, int out_size)
{
    (void)in_sizes; (void)n_in; (void)out_size;
    const float* x     = (const float*)d_in[0];
    const float* w_qkv = (const float*)d_in[1];
    const float* b_qkv = (const float*)d_in[2];
    const float* w_out = (const float*)d_in[3];
    const float* b_out = (const float*)d_in[4];
    const float* pos   = (const float*)d_in[5];
    float* out = (float*)d_out;

    cudaFuncSetAttribute(hmma_gemm<1>, cudaFuncAttributeMaxDynamicSharedMemorySize, GEMM_SMEM);
    cudaFuncSetAttribute(hmma_gemm<0>, cudaFuncAttributeMaxDynamicSharedMemorySize, GEMM_SMEM);
    cudaFuncSetAttribute(attn2, cudaFuncAttributeMaxDynamicSharedMemorySize, ATT_SMEM);

    // 0) convert input to fp16 + transpose/split weights (fp16 hi/lo)
    conv_kernel<<<MTOT * DIMC / 1024, 256>>>(x);
    transpose_split<0><<<dim3(N_QKV / 32, DIMC / 32), dim3(32, 8)>>>(w_qkv);
    transpose_split<1><<<dim3(DIMC / 32, DIMC / 32), dim3(32, 8)>>>(w_out);

    // 1) QKV projection + bias (+pos, q-scale) -> fp16 Q hi/lo, K, V
    hmma_gemm<1><<<dim3(N_QKV / 128, MTOT / 128), 256, GEMM_SMEM>>>(b_qkv, pos, nullptr);

    // 2) HMMA flash attention -> fp16 attn out
    attn2<<<dim3(TT / 128, BB * NH), 256, ATT_SMEM>>>();

    // 3) output projection + bias
    hmma_gemm<0><<<dim3(DIMC / 128, MTOT / 128), 256, GEMM_SMEM>>>(b_out, nullptr, out);
}